// round 4
// baseline (speedup 1.0000x reference)
#include <cuda_runtime.h>
#include <cuda_bf16.h>
#include <cstdint>

#define BB 4
#define NN 16384
#define MM 16384
#define HH 32
#define KK 15
#define FF 64
#define CC 64
#define KF 960
#define TOTALP (BB * MM)      // 65536

// ---------------- Phase-A (HMMA) config ----------------
#define PW 8                  // points per warp
#define THREADS_A 256         // 8 warps
#define FEAT_STRIDE 68        // words per h-row of featHL
#define WHL_STRIDE 40         // words per k-row of whl
#define WARP_WORDS (HH * FEAT_STRIDE + 16 * WHL_STRIDE)   // 2176+640 = 2816
#define SMEM_A (8 * WARP_WORDS * 4)                       // 90112 B

// ---------------- GEMM config -------------------
#define PTS_CTA 256
#define THREADS_G 256
#define KCH 64
#define NCH (KF / KCH)        // 15
#define ROWB 144

#define OFF_WFHI 0
#define OFF_WFLO (PTS_CTA * ROWB)
#define OFF_KVHI (2 * PTS_CTA * ROWB)
#define OFF_KVLO (OFF_KVHI + CC * ROWB)
#define SMEM_G   (OFF_KVLO + CC * ROWB)

// ------------- device scratch -------------
__device__ __nv_bfloat16 g_WFhi[(size_t)TOTALP * KF];
__device__ __nv_bfloat16 g_WFlo[(size_t)TOTALP * KF];
__device__ __nv_bfloat16 g_KVThi[CC * KF];
__device__ __nv_bfloat16 g_KVTlo[CC * KF];

// ------------- helpers -------------
__device__ __forceinline__ uint32_t smem_u32(const void* p) {
    uint32_t a;
    asm("{ .reg .u64 t; cvta.to.shared.u64 t, %1; cvt.u32.u64 %0, t; }" : "=r"(a) : "l"(p));
    return a;
}
__device__ __forceinline__ void cpasync16(uint32_t dst, const void* src) {
    asm volatile("cp.async.cg.shared.global [%0], [%1], 16;" :: "r"(dst), "l"(src));
}
__device__ __forceinline__ void cpasync_commit() { asm volatile("cp.async.commit_group;"); }
__device__ __forceinline__ void cpasync_wait0()  { asm volatile("cp.async.wait_group 0;" ::: "memory"); }
__device__ __forceinline__ uint32_t lds32(uint32_t a) {
    uint32_t v; asm volatile("ld.shared.b32 %0, [%1];" : "=r"(v) : "r"(a)); return v;
}
__device__ __forceinline__ void mma16816(float* c, const uint32_t* a, const uint32_t* b) {
    asm volatile(
        "mma.sync.aligned.m16n8k16.row.col.f32.bf16.bf16.f32 "
        "{%0,%1,%2,%3}, {%4,%5,%6,%7}, {%8,%9}, {%0,%1,%2,%3};"
        : "+f"(c[0]), "+f"(c[1]), "+f"(c[2]), "+f"(c[3])
        : "r"(a[0]), "r"(a[1]), "r"(a[2]), "r"(a[3]), "r"(b[0]), "r"(b[1]));
}
__device__ __forceinline__ void pack_hl2(float x, float y, uint32_t& hi2, uint32_t& lo2) {
    __nv_bfloat162 h = __floats2bfloat162_rn(x, y);
    hi2 = *(uint32_t*)&h;
    float lx = x - __low2float(h);
    float ly = y - __high2float(h);
    __nv_bfloat162 l = __floats2bfloat162_rn(lx, ly);
    lo2 = *(uint32_t*)&l;
}

// =================================================================
// Kernel 0: k_values [kf][c] -> KVT hi/lo [c][kf]
// =================================================================
__global__ void prep_kvt_kernel(const float* __restrict__ k_values) {
    int i = blockIdx.x * blockDim.x + threadIdx.x;
    if (i >= KF * CC) return;
    const int kf = i >> 6, c = i & 63;
    const float v = k_values[i];
    const __nv_bfloat16 hi = __float2bfloat16(v);
    g_KVThi[c * KF + kf] = hi;
    g_KVTlo[c * KF + kf] = __float2bfloat16(v - __bfloat162float(hi));
}

// =================================================================
// Kernel 1: Phase A via HMMA: wf[16k][64f] = w^T[16][32] @ feat[32][64]
// =================================================================
__global__ void __launch_bounds__(THREADS_A, 2)
phaseA_kernel(const float* __restrict__ points,
              const float* __restrict__ features,
              const float* __restrict__ output_points,
              const float* __restrict__ k_points,
              const int*   __restrict__ neighbor_indices)
{
    extern __shared__ uint32_t smemA[];
    __shared__ float kpss[KK * 3 + 3];

    const int tid  = threadIdx.x;
    const int warp = tid >> 5;
    const int lane = tid & 31;
    const int g    = lane >> 2;
    const int t    = lane & 3;

    if (tid < KK * 3) kpss[tid] = k_points[tid];
    __syncthreads();

    uint32_t* featHL = smemA + warp * WARP_WORDS;          // [32][68]
    uint32_t* whl    = featHL + HH * FEAT_STRIDE;          // [16][40]
    uint32_t* bufh   = featHL;                             // reuse: [16][36]
    uint32_t* bufl   = featHL + 16 * 36;

    for (int pi = 0; pi < PW; pi++) {
        const int gp = (blockIdx.x * 8 + warp) * PW + pi;
        const int b  = gp >> 14;

        // ---- w computation: lane = h ----
        const int nidx = neighbor_indices[gp * HH + lane];
        const float ox = output_points[gp * 3 + 0];
        const float oy = output_points[gp * 3 + 1];
        const float oz = output_points[gp * 3 + 2];
        const float* pp = points + ((size_t)b * NN + nidx) * 3;
        const float rx = pp[0] - ox;
        const float ry = pp[1] - oy;
        const float rz = pp[2] - oz;

        #pragma unroll
        for (int k = 0; k < KK; k++) {
            const float dx = rx - kpss[k * 3 + 0];
            const float dy = ry - kpss[k * 3 + 1];
            const float dz = rz - kpss[k * 3 + 2];
            const float d  = sqrtf(fmaf(dx, dx, fmaf(dy, dy, dz * dz)));
            const float w  = fmaxf(1.0f - d, 0.0f);
            const __nv_bfloat16 hb = __float2bfloat16(w);
            const float lw = w - __bfloat162float(hb);
            const __nv_bfloat16 lb = __float2bfloat16(lw);
            whl[k * WHL_STRIDE + lane] =
                ((uint32_t)(*(const uint16_t*)&hb) << 16) | (uint32_t)(*(const uint16_t*)&lb);
        }
        whl[15 * WHL_STRIDE + lane] = 0u;

        // ---- gather feat rows -> featHL[h][f] as (hi<<16|lo) words ----
        const float* fbase = features + (size_t)b * NN * FF;
        #pragma unroll 4
        for (int h = 0; h < HH; h++) {
            const int ni = __shfl_sync(0xffffffffu, nidx, h);
            const float2 f2 = *(const float2*)(fbase + (size_t)ni * FF + 2 * lane);
            uint32_t hi2, lo2;
            pack_hl2(f2.x, f2.y, hi2, lo2);
            const uint32_t HL0 = __byte_perm(hi2, lo2, 0x1054);
            const uint32_t HL1 = __byte_perm(hi2, lo2, 0x3276);
            *(uint2*)(featHL + h * FEAT_STRIDE + 2 * lane) = make_uint2(HL0, HL1);
        }
        __syncwarp();

        // ---- MMA ----
        float acc[8][4];
        #pragma unroll
        for (int ft = 0; ft < 8; ft++)
            #pragma unroll
            for (int q = 0; q < 4; q++) acc[ft][q] = 0.0f;

        #pragma unroll
        for (int ks = 0; ks < 2; ks++) {
            const int h0 = ks * 16 + 2 * t;
            uint32_t ah[4], al[4];
            {
                const uint2 wlo  = *(const uint2*)(whl + g * WHL_STRIDE + h0);
                const uint2 wlo8 = *(const uint2*)(whl + (g + 8) * WHL_STRIDE + h0);
                const uint2 whiA = *(const uint2*)(whl + g * WHL_STRIDE + h0 + 8);
                const uint2 whiB = *(const uint2*)(whl + (g + 8) * WHL_STRIDE + h0 + 8);
                ah[0] = __byte_perm(wlo.x,  wlo.y,  0x7632); al[0] = __byte_perm(wlo.x,  wlo.y,  0x5410);
                ah[1] = __byte_perm(wlo8.x, wlo8.y, 0x7632); al[1] = __byte_perm(wlo8.x, wlo8.y, 0x5410);
                ah[2] = __byte_perm(whiA.x, whiA.y, 0x7632); al[2] = __byte_perm(whiA.x, whiA.y, 0x5410);
                ah[3] = __byte_perm(whiB.x, whiB.y, 0x7632); al[3] = __byte_perm(whiB.x, whiB.y, 0x5410);
            }
            #pragma unroll
            for (int ft = 0; ft < 8; ft++) {
                const int f = ft * 8 + g;
                const uint32_t u0 = featHL[(h0)     * FEAT_STRIDE + f];
                const uint32_t u1 = featHL[(h0 + 1) * FEAT_STRIDE + f];
                const uint32_t u2 = featHL[(h0 + 8) * FEAT_STRIDE + f];
                const uint32_t u3 = featHL[(h0 + 9) * FEAT_STRIDE + f];
                uint32_t bh[2], bl[2];
                bh[0] = __byte_perm(u0, u1, 0x7632); bl[0] = __byte_perm(u0, u1, 0x5410);
                bh[1] = __byte_perm(u2, u3, 0x7632); bl[1] = __byte_perm(u2, u3, 0x5410);
                mma16816(acc[ft], ah, bh);
                mma16816(acc[ft], ah, bl);
                mma16816(acc[ft], al, bh);
            }
        }
        __syncwarp();

        // ---- epilogue: stage into buf, then coalesced STG ----
        #pragma unroll
        for (int ft = 0; ft < 8; ft++) {
            uint32_t h2, l2;
            pack_hl2(acc[ft][0], acc[ft][1], h2, l2);
            bufh[g * 36 + ft * 4 + t] = h2;
            bufl[g * 36 + ft * 4 + t] = l2;
            pack_hl2(acc[ft][2], acc[ft][3], h2, l2);
            bufh[(g + 8) * 36 + ft * 4 + t] = h2;
            bufl[(g + 8) * 36 + ft * 4 + t] = l2;
        }
        __syncwarp();

        uint32_t* dsth = (uint32_t*)g_WFhi + (size_t)gp * (KF / 2);
        uint32_t* dstl = (uint32_t*)g_WFlo + (size_t)gp * (KF / 2);
        #pragma unroll
        for (int i = 0; i < 15; i++) {
            dsth[i * 32 + lane] = bufh[i * 36 + lane];
            dstl[i * 32 + lane] = bufl[i * 36 + lane];
        }
        __syncwarp();
    }
}

// =================================================================
// Kernel 2: out = WF @ KVT^T via mma.sync (validated R3 kernel)
// =================================================================
__global__ void __launch_bounds__(THREADS_G, 2)
gemm_kernel(float* __restrict__ out)
{
    extern __shared__ char smem[];
    const uint32_t smb = smem_u32(smem);

    const int tid  = threadIdx.x;
    const int wid  = tid >> 5;
    const int lane = tid & 31;
    const int g    = lane >> 2;
    const int t    = lane & 3;
    const int m0   = blockIdx.x * PTS_CTA;
    const int pbase = wid * 32;

    float acc[4][4][4];
    #pragma unroll
    for (int i = 0; i < 4; i++)
        #pragma unroll
        for (int j = 0; j < 4; j++)
            #pragma unroll
            for (int q = 0; q < 4; q++) acc[i][j][q] = 0.0f;

    for (int ch = 0; ch < NCH; ch++) {
        __syncthreads();
        const size_t koff = (size_t)ch * KCH;
        for (int u = tid; u < PTS_CTA * 8; u += THREADS_G) {
            const int r = u >> 3, s = u & 7;
            const size_t src = (size_t)(m0 + r) * KF + koff + s * 8;
            const uint32_t d = smb + OFF_WFHI + r * ROWB + s * 16;
            cpasync16(d, g_WFhi + src);
            cpasync16(d + (OFF_WFLO - OFF_WFHI), g_WFlo + src);
        }
        for (int u = tid; u < CC * 8; u += THREADS_G) {
            const int r = u >> 3, s = u & 7;
            const size_t src = (size_t)r * KF + koff + s * 8;
            const uint32_t d = smb + OFF_KVHI + r * ROWB + s * 16;
            cpasync16(d, g_KVThi + src);
            cpasync16(d + (OFF_KVLO - OFF_KVHI), g_KVTlo + src);
        }
        cpasync_commit();
        cpasync_wait0();
        __syncthreads();

        #pragma unroll
        for (int ks = 0; ks < KCH / 16; ks++) {
            const int kbB = ks * 32;

            uint32_t bh[4][2], bl[4][2];
            #pragma unroll
            for (int pt = 0; pt < 4; pt++) {
                const uint32_t rowoff = (pbase + pt * 8 + g) * ROWB + kbB + t * 4;
                bh[pt][0] = lds32(smb + OFF_WFHI + rowoff);
                bh[pt][1] = lds32(smb + OFF_WFHI + rowoff + 16);
                bl[pt][0] = lds32(smb + OFF_WFLO + rowoff);
                bl[pt][1] = lds32(smb + OFF_WFLO + rowoff + 16);
            }

            #pragma unroll
            for (int cm = 0; cm < 4; cm++) {
                const uint32_t rowoff = (cm * 16 + g) * ROWB + kbB + t * 4;
                uint32_t ah[4], al[4];
                ah[0] = lds32(smb + OFF_KVHI + rowoff);
                ah[1] = lds32(smb + OFF_KVHI + rowoff + 8 * ROWB);
                ah[2] = lds32(smb + OFF_KVHI + rowoff + 16);
                ah[3] = lds32(smb + OFF_KVHI + rowoff + 8 * ROWB + 16);
                al[0] = lds32(smb + OFF_KVLO + rowoff);
                al[1] = lds32(smb + OFF_KVLO + rowoff + 8 * ROWB);
                al[2] = lds32(smb + OFF_KVLO + rowoff + 16);
                al[3] = lds32(smb + OFF_KVLO + rowoff + 8 * ROWB + 16);

                #pragma unroll
                for (int pt = 0; pt < 4; pt++) {
                    mma16816(acc[cm][pt], ah, bh[pt]);
                    mma16816(acc[cm][pt], ah, bl[pt]);
                    mma16816(acc[cm][pt], al, bh[pt]);
                }
            }
        }
    }

    #pragma unroll
    for (int cm = 0; cm < 4; cm++) {
        #pragma unroll
        for (int pt = 0; pt < 4; pt++) {
            const int c0 = cm * 16 + g;
            const int c1 = c0 + 8;
            const size_t p0 = (size_t)m0 + pbase + pt * 8 + t * 2;
            out[p0 * CC + c0]       = acc[cm][pt][0];
            out[(p0 + 1) * CC + c0] = acc[cm][pt][1];
            out[p0 * CC + c1]       = acc[cm][pt][2];
            out[(p0 + 1) * CC + c1] = acc[cm][pt][3];
        }
    }
}

// =================================================================
extern "C" void kernel_launch(void* const* d_in, const int* in_sizes, int n_in,
                              void* d_out, int out_size)
{
    const float* points        = (const float*)d_in[0];
    const float* features      = (const float*)d_in[1];
    const float* output_points = (const float*)d_in[2];
    const float* k_points      = (const float*)d_in[3];
    const float* k_values      = (const float*)d_in[4];
    const int*   neighbor_idx  = (const int*)d_in[5];
    float* out = (float*)d_out;

    static bool attr_done = false;
    if (!attr_done) {
        cudaFuncSetAttribute(gemm_kernel, cudaFuncAttributeMaxDynamicSharedMemorySize, SMEM_G);
        cudaFuncSetAttribute(phaseA_kernel, cudaFuncAttributeMaxDynamicSharedMemorySize, SMEM_A);
        attr_done = true;
    }

    prep_kvt_kernel<<<(KF * CC + 255) / 256, 256>>>(k_values);
    phaseA_kernel<<<TOTALP / (8 * PW), THREADS_A, SMEM_A>>>(
        points, features, output_points, k_points, neighbor_idx);
    gemm_kernel<<<TOTALP / PTS_CTA, THREADS_G, SMEM_G>>>(out);
}

// round 5
// speedup vs baseline: 1.0249x; 1.0249x over previous
#include <cuda_runtime.h>
#include <cuda_bf16.h>
#include <cstdint>

#define BB 4
#define NN 16384
#define MM 16384
#define HH 32
#define KK 15
#define FF 64
#define CC 64
#define KF 960
#define TOTALP (BB * MM)      // 65536

// ---------------- Phase-A config ----------------
#define TPB 16
#define THREADS_A 512

// ---------------- GEMM config -------------------
#define PTS_CTA 256
#define THREADS_G 256
#define KCH 64
#define NCH (KF / KCH)        // 15
#define ROWB 144

#define OFF_WFHI 0
#define OFF_WFLO (PTS_CTA * ROWB)
#define OFF_KVHI (2 * PTS_CTA * ROWB)
#define OFF_KVLO (OFF_KVHI + CC * ROWB)
#define SMEM_G   (OFF_KVLO + CC * ROWB)

typedef unsigned long long u64;

// ------------- device scratch -------------
__device__ __nv_bfloat16 g_WFhi[(size_t)TOTALP * KF];
__device__ __nv_bfloat16 g_WFlo[(size_t)TOTALP * KF];
__device__ __nv_bfloat16 g_KVThi[CC * KF];
__device__ __nv_bfloat16 g_KVTlo[CC * KF];

// ------------- helpers -------------
__device__ __forceinline__ uint32_t smem_u32(const void* p) {
    uint32_t a;
    asm("{ .reg .u64 t; cvta.to.shared.u64 t, %1; cvt.u32.u64 %0, t; }" : "=r"(a) : "l"(p));
    return a;
}
__device__ __forceinline__ void cpasync16(uint32_t dst, const void* src) {
    asm volatile("cp.async.cg.shared.global [%0], [%1], 16;" :: "r"(dst), "l"(src));
}
__device__ __forceinline__ void cpasync_commit() { asm volatile("cp.async.commit_group;"); }
__device__ __forceinline__ void cpasync_wait0()  { asm volatile("cp.async.wait_group 0;" ::: "memory"); }
__device__ __forceinline__ uint32_t lds32(uint32_t a) {
    uint32_t v; asm volatile("ld.shared.b32 %0, [%1];" : "=r"(v) : "r"(a)); return v;
}
__device__ __forceinline__ void mma16816(float* c, const uint32_t* a, const uint32_t* b) {
    asm volatile(
        "mma.sync.aligned.m16n8k16.row.col.f32.bf16.bf16.f32 "
        "{%0,%1,%2,%3}, {%4,%5,%6,%7}, {%8,%9}, {%0,%1,%2,%3};"
        : "+f"(c[0]), "+f"(c[1]), "+f"(c[2]), "+f"(c[3])
        : "r"(a[0]), "r"(a[1]), "r"(a[2]), "r"(a[3]), "r"(b[0]), "r"(b[1]));
}
// ---- packed f32x2 ----
__device__ __forceinline__ u64 pack2(float x, float y) {
    u64 r; asm("mov.b64 %0, {%1, %2};" : "=l"(r) : "f"(x), "f"(y)); return r;
}
__device__ __forceinline__ void unpack2(u64 v, float& x, float& y) {
    asm("mov.b64 {%0, %1}, %2;" : "=f"(x), "=f"(y) : "l"(v));
}
__device__ __forceinline__ void fma2(u64& acc, u64 a, u64 b) {
    asm("fma.rn.f32x2 %0, %1, %2, %0;" : "+l"(acc) : "l"(a), "l"(b));
}

// =================================================================
// Kernel 0: k_values [kf][c] -> KVT hi/lo [c][kf]
// =================================================================
__global__ void prep_kvt_kernel(const float* __restrict__ k_values) {
    int i = blockIdx.x * blockDim.x + threadIdx.x;
    if (i >= KF * CC) return;
    const int kf = i >> 6, c = i & 63;
    const float v = k_values[i];
    const __nv_bfloat16 hi = __float2bfloat16(v);
    g_KVThi[c * KF + kf] = hi;
    g_KVTlo[c * KF + kf] = __float2bfloat16(v - __bfloat162float(hi));
}

// =================================================================
// Kernel 1: Phase A (scalar, f32x2-packed FMA) -> WF bf16 hi/lo
//   acc pairs over k: j -> (k=2j, k=2j+1); k=15 is a zero pad.
// =================================================================
#define WSM_ELEMS (TPB * HH * 16)
#define IDX_ELEMS (TPB * HH)
#define KP_ELEMS  (KK * 3)

__global__ void __launch_bounds__(THREADS_A)
phaseA_kernel(const float* __restrict__ points,
              const float* __restrict__ features,
              const float* __restrict__ output_points,
              const float* __restrict__ k_points,
              const int*   __restrict__ neighbor_indices)
{
    __shared__ float wsm[WSM_ELEMS];      // [warp][h][16 k-padded]
    __shared__ int   idxs[IDX_ELEMS];
    __shared__ float kps[KP_ELEMS + 3];

    const int tid  = threadIdx.x;
    const int warp = tid >> 5;
    const int lane = tid & 31;

    if (tid < KP_ELEMS) kps[tid] = k_points[tid];
    __syncthreads();

    const int gp = blockIdx.x * TPB + warp;
    const int b  = gp >> 14;
    const float ox = output_points[gp * 3 + 0];
    const float oy = output_points[gp * 3 + 1];
    const float oz = output_points[gp * 3 + 2];

    const int nidx = neighbor_indices[gp * HH + lane];
    idxs[warp * HH + lane] = nidx;
    const float* pp = points + ((size_t)b * NN + nidx) * 3;
    const float rx = pp[0] - ox;
    const float ry = pp[1] - oy;
    const float rz = pp[2] - oz;

    float* wrow_mine = wsm + warp * (HH * 16) + lane * 16;
    #pragma unroll
    for (int k = 0; k < KK; k++) {
        const float dx = rx - kps[k * 3 + 0];
        const float dy = ry - kps[k * 3 + 1];
        const float dz = rz - kps[k * 3 + 2];
        const float d  = sqrtf(fmaf(dx, dx, fmaf(dy, dy, dz * dz)));
        wrow_mine[k] = fmaxf(1.0f - d, 0.0f);
    }
    wrow_mine[15] = 0.0f;
    __syncwarp();

    // 8 k-pairs per feature column; lane owns f = 2*lane, 2*lane+1
    u64 accA[8], accB[8];
    #pragma unroll
    for (int j = 0; j < 8; j++) { accA[j] = 0ull; accB[j] = 0ull; }

    const float* fbase = features + (size_t)b * NN * FF;
    const int*   idxw  = idxs + warp * HH;
    const ulonglong2* wbase = (const ulonglong2*)(wsm + warp * (HH * 16));

    #pragma unroll 4
    for (int h = 0; h < HH; h++) {
        const int ni = idxw[h];
        const float2 fv = *(const float2*)(fbase + (size_t)ni * FF + 2 * lane);
        const u64 fa2 = pack2(fv.x, fv.x);
        const u64 fb2 = pack2(fv.y, fv.y);
        // 4x LDS.128 -> 8 packed w-pairs
        const ulonglong2 p0 = wbase[h * 4 + 0];
        const ulonglong2 p1 = wbase[h * 4 + 1];
        const ulonglong2 p2 = wbase[h * 4 + 2];
        const ulonglong2 p3 = wbase[h * 4 + 3];
        const u64 wp[8] = {p0.x, p0.y, p1.x, p1.y, p2.x, p2.y, p3.x, p3.y};
        #pragma unroll
        for (int j = 0; j < 8; j++) {
            fma2(accA[j], wp[j], fa2);
            fma2(accB[j], wp[j], fb2);
        }
    }

    __nv_bfloat162* whi = (__nv_bfloat162*)(g_WFhi + (size_t)gp * KF);
    __nv_bfloat162* wlo = (__nv_bfloat162*)(g_WFlo + (size_t)gp * KF);
    #pragma unroll
    for (int j = 0; j < 8; j++) {
        float a0, a1, b0, b1;
        unpack2(accA[j], a0, a1);   // k=2j (a0), k=2j+1 (a1), feature f0
        unpack2(accB[j], b0, b1);   //                         feature f1
        {   // k = 2j
            const __nv_bfloat162 h2 = __floats2bfloat162_rn(a0, b0);
            whi[(2 * j) * 32 + lane] = h2;
            wlo[(2 * j) * 32 + lane] =
                __floats2bfloat162_rn(a0 - __low2float(h2), b0 - __high2float(h2));
        }
        if (j < 7) {   // k = 2j+1 (skip k=15 pad)
            const __nv_bfloat162 h2 = __floats2bfloat162_rn(a1, b1);
            whi[(2 * j + 1) * 32 + lane] = h2;
            wlo[(2 * j + 1) * 32 + lane] =
                __floats2bfloat162_rn(a1 - __low2float(h2), b1 - __high2float(h2));
        }
    }
}

// =================================================================
// Kernel 2: out = WF @ KVT^T via mma.sync (validated R3 kernel)
// =================================================================
__global__ void __launch_bounds__(THREADS_G, 2)
gemm_kernel(float* __restrict__ out)
{
    extern __shared__ char smem[];
    const uint32_t smb = smem_u32(smem);

    const int tid  = threadIdx.x;
    const int wid  = tid >> 5;
    const int lane = tid & 31;
    const int g    = lane >> 2;
    const int t    = lane & 3;
    const int m0   = blockIdx.x * PTS_CTA;
    const int pbase = wid * 32;

    float acc[4][4][4];
    #pragma unroll
    for (int i = 0; i < 4; i++)
        #pragma unroll
        for (int j = 0; j < 4; j++)
            #pragma unroll
            for (int q = 0; q < 4; q++) acc[i][j][q] = 0.0f;

    for (int ch = 0; ch < NCH; ch++) {
        __syncthreads();
        const size_t koff = (size_t)ch * KCH;
        for (int u = tid; u < PTS_CTA * 8; u += THREADS_G) {
            const int r = u >> 3, s = u & 7;
            const size_t src = (size_t)(m0 + r) * KF + koff + s * 8;
            const uint32_t d = smb + OFF_WFHI + r * ROWB + s * 16;
            cpasync16(d, g_WFhi + src);
            cpasync16(d + (OFF_WFLO - OFF_WFHI), g_WFlo + src);
        }
        for (int u = tid; u < CC * 8; u += THREADS_G) {
            const int r = u >> 3, s = u & 7;
            const size_t src = (size_t)r * KF + koff + s * 8;
            const uint32_t d = smb + OFF_KVHI + r * ROWB + s * 16;
            cpasync16(d, g_KVThi + src);
            cpasync16(d + (OFF_KVLO - OFF_KVHI), g_KVTlo + src);
        }
        cpasync_commit();
        cpasync_wait0();
        __syncthreads();

        #pragma unroll
        for (int ks = 0; ks < KCH / 16; ks++) {
            const int kbB = ks * 32;

            uint32_t bh[4][2], bl[4][2];
            #pragma unroll
            for (int pt = 0; pt < 4; pt++) {
                const uint32_t rowoff = (pbase + pt * 8 + g) * ROWB + kbB + t * 4;
                bh[pt][0] = lds32(smb + OFF_WFHI + rowoff);
                bh[pt][1] = lds32(smb + OFF_WFHI + rowoff + 16);
                bl[pt][0] = lds32(smb + OFF_WFLO + rowoff);
                bl[pt][1] = lds32(smb + OFF_WFLO + rowoff + 16);
            }

            #pragma unroll
            for (int cm = 0; cm < 4; cm++) {
                const uint32_t rowoff = (cm * 16 + g) * ROWB + kbB + t * 4;
                uint32_t ah[4], al[4];
                ah[0] = lds32(smb + OFF_KVHI + rowoff);
                ah[1] = lds32(smb + OFF_KVHI + rowoff + 8 * ROWB);
                ah[2] = lds32(smb + OFF_KVHI + rowoff + 16);
                ah[3] = lds32(smb + OFF_KVHI + rowoff + 8 * ROWB + 16);
                al[0] = lds32(smb + OFF_KVLO + rowoff);
                al[1] = lds32(smb + OFF_KVLO + rowoff + 8 * ROWB);
                al[2] = lds32(smb + OFF_KVLO + rowoff + 16);
                al[3] = lds32(smb + OFF_KVLO + rowoff + 8 * ROWB + 16);

                #pragma unroll
                for (int pt = 0; pt < 4; pt++) {
                    mma16816(acc[cm][pt], ah, bh[pt]);
                    mma16816(acc[cm][pt], ah, bl[pt]);
                    mma16816(acc[cm][pt], al, bh[pt]);
                }
            }
        }
    }

    #pragma unroll
    for (int cm = 0; cm < 4; cm++) {
        #pragma unroll
        for (int pt = 0; pt < 4; pt++) {
            const int c0 = cm * 16 + g;
            const int c1 = c0 + 8;
            const size_t p0 = (size_t)m0 + pbase + pt * 8 + t * 2;
            out[p0 * CC + c0]       = acc[cm][pt][0];
            out[(p0 + 1) * CC + c0] = acc[cm][pt][1];
            out[p0 * CC + c1]       = acc[cm][pt][2];
            out[(p0 + 1) * CC + c1] = acc[cm][pt][3];
        }
    }
}

// =================================================================
extern "C" void kernel_launch(void* const* d_in, const int* in_sizes, int n_in,
                              void* d_out, int out_size)
{
    const float* points        = (const float*)d_in[0];
    const float* features      = (const float*)d_in[1];
    const float* output_points = (const float*)d_in[2];
    const float* k_points      = (const float*)d_in[3];
    const float* k_values      = (const float*)d_in[4];
    const int*   neighbor_idx  = (const int*)d_in[5];
    float* out = (float*)d_out;

    static bool attr_done = false;
    if (!attr_done) {
        cudaFuncSetAttribute(gemm_kernel, cudaFuncAttributeMaxDynamicSharedMemorySize, SMEM_G);
        attr_done = true;
    }

    prep_kvt_kernel<<<(KF * CC + 255) / 256, 256>>>(k_values);
    phaseA_kernel<<<TOTALP / TPB, THREADS_A>>>(
        points, features, output_points, k_points, neighbor_idx);
    gemm_kernel<<<TOTALP / PTS_CTA, THREADS_G, SMEM_G>>>(out);
}

// round 6
// speedup vs baseline: 1.2228x; 1.1931x over previous
#include <cuda_runtime.h>
#include <cuda_fp16.h>
#include <cstdint>

#define BB 4
#define NN 16384
#define MM 16384
#define HH 32
#define KK 15
#define FF 64
#define CC 64
#define KF 960
#define TOTALP (BB * MM)      // 65536

// ---------------- Phase-A config ----------------
#define TPB 16
#define THREADS_A 512

// ---------------- GEMM config -------------------
#define PTS_CTA 256
#define THREADS_G 256
#define KCH 64                // fp16 K-elements per chunk (128B rows)
#define NCH (KF / KCH)        // 15
#define ROWB 144              // padded row stride (bytes)

// stage layout (bytes, per pipeline stage)
#define ST_WF   0
#define ST_KVHI (PTS_CTA * ROWB)            // 36864
#define ST_KVLO (ST_KVHI + CC * ROWB)       // 46080
#define ST_SIZE (ST_KVLO + CC * ROWB)       // 55296
#define SMEM_G  (2 * ST_SIZE)               // 110592

typedef unsigned long long u64;

// ------------- device scratch -------------
__device__ __half g_WFhi[(size_t)TOTALP * KF];   // 120 MB (fp16, single precision level)
__device__ __half g_KVThi[CC * KF];              // [c][kf]
__device__ __half g_KVTlo[CC * KF];

// ------------- helpers -------------
__device__ __forceinline__ uint32_t smem_u32(const void* p) {
    uint32_t a;
    asm("{ .reg .u64 t; cvta.to.shared.u64 t, %1; cvt.u32.u64 %0, t; }" : "=r"(a) : "l"(p));
    return a;
}
__device__ __forceinline__ void cpasync16(uint32_t dst, const void* src) {
    asm volatile("cp.async.cg.shared.global [%0], [%1], 16;" :: "r"(dst), "l"(src));
}
__device__ __forceinline__ void cpasync_commit() { asm volatile("cp.async.commit_group;"); }
__device__ __forceinline__ uint32_t lds32(uint32_t a) {
    uint32_t v; asm volatile("ld.shared.b32 %0, [%1];" : "=r"(v) : "r"(a)); return v;
}
__device__ __forceinline__ void mma16816h(float* c, const uint32_t* a, const uint32_t* b) {
    asm volatile(
        "mma.sync.aligned.m16n8k16.row.col.f32.f16.f16.f32 "
        "{%0,%1,%2,%3}, {%4,%5,%6,%7}, {%8,%9}, {%0,%1,%2,%3};"
        : "+f"(c[0]), "+f"(c[1]), "+f"(c[2]), "+f"(c[3])
        : "r"(a[0]), "r"(a[1]), "r"(a[2]), "r"(a[3]), "r"(b[0]), "r"(b[1]));
}
// ---- packed f32x2 ----
__device__ __forceinline__ u64 pack2(float x, float y) {
    u64 r; asm("mov.b64 %0, {%1, %2};" : "=l"(r) : "f"(x), "f"(y)); return r;
}
__device__ __forceinline__ void unpack2(u64 v, float& x, float& y) {
    asm("mov.b64 {%0, %1}, %2;" : "=f"(x), "=f"(y) : "l"(v));
}
__device__ __forceinline__ void fma2(u64& acc, u64 a, u64 b) {
    asm("fma.rn.f32x2 %0, %1, %2, %0;" : "+l"(acc) : "l"(a), "l"(b));
}

// =================================================================
// Kernel 1: Phase A (scalar, f32x2 FMA) -> WF fp16
//   Blocks < 120 also transpose k_values -> KVT fp16 hi/lo (gemm runs later).
// =================================================================
#define WSM_ELEMS (TPB * HH * 16)
#define IDX_ELEMS (TPB * HH)
#define KP_ELEMS  (KK * 3)

__global__ void __launch_bounds__(THREADS_A)
phaseA_kernel(const float* __restrict__ points,
              const float* __restrict__ features,
              const float* __restrict__ output_points,
              const float* __restrict__ k_points,
              const float* __restrict__ k_values,
              const int*   __restrict__ neighbor_indices)
{
    __shared__ float wsm[WSM_ELEMS];      // [warp][h][16 k-padded]
    __shared__ int   idxs[IDX_ELEMS];
    __shared__ float kps[KP_ELEMS + 3];

    const int tid  = threadIdx.x;
    const int warp = tid >> 5;
    const int lane = tid & 31;

    // merged KVT prep (120 * 512 = 61440 = KF*CC elements)
    if (blockIdx.x < 120) {
        const int i = blockIdx.x * THREADS_A + tid;
        const int kf = i >> 6, c = i & 63;
        const float v = k_values[i];
        const __half hi = __float2half_rn(v);
        g_KVThi[c * KF + kf] = hi;
        g_KVTlo[c * KF + kf] = __float2half_rn(v - __half2float(hi));
    }

    if (tid < KP_ELEMS) kps[tid] = k_points[tid];
    __syncthreads();

    const int gp = blockIdx.x * TPB + warp;
    const int b  = gp >> 14;
    const float ox = output_points[gp * 3 + 0];
    const float oy = output_points[gp * 3 + 1];
    const float oz = output_points[gp * 3 + 2];

    const int nidx = neighbor_indices[gp * HH + lane];
    idxs[warp * HH + lane] = nidx;
    const float* pp = points + ((size_t)b * NN + nidx) * 3;
    const float rx = pp[0] - ox;
    const float ry = pp[1] - oy;
    const float rz = pp[2] - oz;

    float* wrow_mine = wsm + warp * (HH * 16) + lane * 16;
    #pragma unroll
    for (int k = 0; k < KK; k++) {
        const float dx = rx - kps[k * 3 + 0];
        const float dy = ry - kps[k * 3 + 1];
        const float dz = rz - kps[k * 3 + 2];
        const float d  = sqrtf(fmaf(dx, dx, fmaf(dy, dy, dz * dz)));
        wrow_mine[k] = fmaxf(1.0f - d, 0.0f);
    }
    wrow_mine[15] = 0.0f;
    __syncwarp();

    // 8 k-pairs; lane owns f = 2*lane, 2*lane+1
    u64 accA[8], accB[8];
    #pragma unroll
    for (int j = 0; j < 8; j++) { accA[j] = 0ull; accB[j] = 0ull; }

    const float* fbase = features + (size_t)b * NN * FF;
    const int*   idxw  = idxs + warp * HH;
    const ulonglong2* wbase = (const ulonglong2*)(wsm + warp * (HH * 16));

    #pragma unroll 4
    for (int h = 0; h < HH; h++) {
        const int ni = idxw[h];
        const float2 fv = *(const float2*)(fbase + (size_t)ni * FF + 2 * lane);
        const u64 fa2 = pack2(fv.x, fv.x);
        const u64 fb2 = pack2(fv.y, fv.y);
        const ulonglong2 p0 = wbase[h * 4 + 0];
        const ulonglong2 p1 = wbase[h * 4 + 1];
        const ulonglong2 p2 = wbase[h * 4 + 2];
        const ulonglong2 p3 = wbase[h * 4 + 3];
        const u64 wp[8] = {p0.x, p0.y, p1.x, p1.y, p2.x, p2.y, p3.x, p3.y};
        #pragma unroll
        for (int j = 0; j < 8; j++) {
            fma2(accA[j], wp[j], fa2);
            fma2(accB[j], wp[j], fb2);
        }
    }

    // store WF fp16: element kf = k*64 + f; half2 word index = k*32 + lane
    __half2* wdst = (__half2*)(g_WFhi + (size_t)gp * KF);
    #pragma unroll
    for (int j = 0; j < 8; j++) {
        float a0, a1, b0, b1;
        unpack2(accA[j], a0, a1);   // k=2j, k=2j+1 for f0
        unpack2(accB[j], b0, b1);   // for f1
        wdst[(2 * j) * 32 + lane] = __floats2half2_rn(a0, b0);
        if (j < 7)
            wdst[(2 * j + 1) * 32 + lane] = __floats2half2_rn(a1, b1);
    }
}

// =================================================================
// Kernel 2: out = WF @ KVT^T, fp16 HMMA, 2-term (kv hi/lo), double-buffered
// =================================================================
__global__ void __launch_bounds__(THREADS_G, 2)
gemm_kernel(float* __restrict__ out)
{
    extern __shared__ char smem[];
    const uint32_t smb = smem_u32(smem);

    const int tid  = threadIdx.x;
    const int wid  = tid >> 5;
    const int lane = tid & 31;
    const int g    = lane >> 2;
    const int t    = lane & 3;
    const int m0   = blockIdx.x * PTS_CTA;
    const int pbase = wid * 32;

    float acc[4][4][4];
    #pragma unroll
    for (int i = 0; i < 4; i++)
        #pragma unroll
        for (int j = 0; j < 4; j++)
            #pragma unroll
            for (int q = 0; q < 4; q++) acc[i][j][q] = 0.0f;

    // ---- stage loader: one commit group per chunk ----
    auto stage_load = [&](int ch, int buf) {
        const size_t koff = (size_t)ch * KCH;
        const uint32_t sb = smb + buf * ST_SIZE;
        #pragma unroll
        for (int u = tid; u < PTS_CTA * 8; u += THREADS_G) {
            const int r = u >> 3, s = u & 7;
            cpasync16(sb + ST_WF + r * ROWB + s * 16,
                      g_WFhi + (size_t)(m0 + r) * KF + koff + s * 8);
        }
        #pragma unroll
        for (int u = tid; u < CC * 8; u += THREADS_G) {
            const int r = u >> 3, s = u & 7;
            const size_t src = (size_t)r * KF + koff + s * 8;
            cpasync16(sb + ST_KVHI + r * ROWB + s * 16, g_KVThi + src);
            cpasync16(sb + ST_KVLO + r * ROWB + s * 16, g_KVTlo + src);
        }
        cpasync_commit();
    };

    stage_load(0, 0);

    for (int ch = 0; ch < NCH; ch++) {
        if (ch + 1 < NCH) {
            stage_load(ch + 1, (ch + 1) & 1);
            asm volatile("cp.async.wait_group 1;" ::: "memory");
        } else {
            asm volatile("cp.async.wait_group 0;" ::: "memory");
        }
        __syncthreads();

        const uint32_t sb = smb + (ch & 1) * ST_SIZE;

        #pragma unroll
        for (int ks = 0; ks < KCH / 16; ks++) {
            const int kbB = ks * 32;   // 16 fp16 = 32 bytes

            uint32_t bh[4][2];
            #pragma unroll
            for (int pt = 0; pt < 4; pt++) {
                const uint32_t rowoff = (pbase + pt * 8 + g) * ROWB + kbB + t * 4;
                bh[pt][0] = lds32(sb + ST_WF + rowoff);
                bh[pt][1] = lds32(sb + ST_WF + rowoff + 16);
            }

            #pragma unroll
            for (int cm = 0; cm < 4; cm++) {
                const uint32_t rowoff = (cm * 16 + g) * ROWB + kbB + t * 4;
                uint32_t ah[4], al[4];
                ah[0] = lds32(sb + ST_KVHI + rowoff);
                ah[1] = lds32(sb + ST_KVHI + rowoff + 8 * ROWB);
                ah[2] = lds32(sb + ST_KVHI + rowoff + 16);
                ah[3] = lds32(sb + ST_KVHI + rowoff + 8 * ROWB + 16);
                al[0] = lds32(sb + ST_KVLO + rowoff);
                al[1] = lds32(sb + ST_KVLO + rowoff + 8 * ROWB);
                al[2] = lds32(sb + ST_KVLO + rowoff + 16);
                al[3] = lds32(sb + ST_KVLO + rowoff + 8 * ROWB + 16);

                #pragma unroll
                for (int pt = 0; pt < 4; pt++) {
                    mma16816h(acc[cm][pt], ah, bh[pt]);
                    mma16816h(acc[cm][pt], al, bh[pt]);
                }
            }
        }
        __syncthreads();   // done reading this buffer before it is re-staged
    }

    #pragma unroll
    for (int cm = 0; cm < 4; cm++) {
        #pragma unroll
        for (int pt = 0; pt < 4; pt++) {
            const int c0 = cm * 16 + g;
            const int c1 = c0 + 8;
            const size_t p0 = (size_t)m0 + pbase + pt * 8 + t * 2;
            out[p0 * CC + c0]       = acc[cm][pt][0];
            out[(p0 + 1) * CC + c0] = acc[cm][pt][1];
            out[p0 * CC + c1]       = acc[cm][pt][2];
            out[(p0 + 1) * CC + c1] = acc[cm][pt][3];
        }
    }
}

// =================================================================
extern "C" void kernel_launch(void* const* d_in, const int* in_sizes, int n_in,
                              void* d_out, int out_size)
{
    const float* points        = (const float*)d_in[0];
    const float* features      = (const float*)d_in[1];
    const float* output_points = (const float*)d_in[2];
    const float* k_points      = (const float*)d_in[3];
    const float* k_values      = (const float*)d_in[4];
    const int*   neighbor_idx  = (const int*)d_in[5];
    float* out = (float*)d_out;

    static bool attr_done = false;
    if (!attr_done) {
        cudaFuncSetAttribute(gemm_kernel, cudaFuncAttributeMaxDynamicSharedMemorySize, SMEM_G);
        attr_done = true;
    }

    phaseA_kernel<<<TOTALP / TPB, THREADS_A>>>(
        points, features, output_points, k_points, k_values, neighbor_idx);
    gemm_kernel<<<TOTALP / PTS_CTA, THREADS_G, SMEM_G>>>(out);
}

// round 7
// speedup vs baseline: 1.5786x; 1.2910x over previous
#include <cuda_runtime.h>
#include <cuda_fp16.h>
#include <cstdint>

#define BB 4
#define NN 16384
#define MM 16384
#define HH 32
#define KK 15
#define FF 64
#define CC 64
#define KF 960
#define TOTALP (BB * MM)      // 65536

// ---------------- Phase-A (HMMA v2) config ----------------
#define THREADS_A 256         // 8 warps, 1 point per warp
#define WARPS_A 8
#define FEATW 72              // halfs per feat row (144B, odd multiple of 16B)
#define WROW  40              // halfs per wT row (80B -> conflict-free a-frags)
#define WARP_HALFS (HH * FEATW + 16 * WROW)   // 2304 + 640 = 2944
#define SMEM_A (WARPS_A * WARP_HALFS * 2)     // 47104 B

// ---------------- GEMM config (validated R6) -------------------
#define PTS_CTA 256
#define THREADS_G 256
#define KCH 64
#define NCH (KF / KCH)        // 15
#define ROWB 144

#define ST_WF   0
#define ST_KVHI (PTS_CTA * ROWB)
#define ST_KVLO (ST_KVHI + CC * ROWB)
#define ST_SIZE (ST_KVLO + CC * ROWB)
#define SMEM_G  (2 * ST_SIZE)

// ------------- device scratch -------------
__device__ __half g_WF[(size_t)TOTALP * KF];     // 120 MB fp16
__device__ __half g_KVThi[CC * KF];              // [c][kf]
__device__ __half g_KVTlo[CC * KF];

// ------------- helpers -------------
__device__ __forceinline__ uint32_t smem_u32(const void* p) {
    uint32_t a;
    asm("{ .reg .u64 t; cvta.to.shared.u64 t, %1; cvt.u32.u64 %0, t; }" : "=r"(a) : "l"(p));
    return a;
}
__device__ __forceinline__ void cpasync16(uint32_t dst, const void* src) {
    asm volatile("cp.async.cg.shared.global [%0], [%1], 16;" :: "r"(dst), "l"(src));
}
__device__ __forceinline__ void cpasync_commit() { asm volatile("cp.async.commit_group;"); }
__device__ __forceinline__ uint32_t lds32(uint32_t a) {
    uint32_t v; asm volatile("ld.shared.b32 %0, [%1];" : "=r"(v) : "r"(a)); return v;
}
__device__ __forceinline__ void mma16816h(float* c, const uint32_t* a, const uint32_t* b) {
    asm volatile(
        "mma.sync.aligned.m16n8k16.row.col.f32.f16.f16.f32 "
        "{%0,%1,%2,%3}, {%4,%5,%6,%7}, {%8,%9}, {%0,%1,%2,%3};"
        : "+f"(c[0]), "+f"(c[1]), "+f"(c[2]), "+f"(c[3])
        : "r"(a[0]), "r"(a[1]), "r"(a[2]), "r"(a[3]), "r"(b[0]), "r"(b[1]));
}
__device__ __forceinline__ void ldmatrix_x4_t(uint32_t& r0, uint32_t& r1,
                                              uint32_t& r2, uint32_t& r3, uint32_t a) {
    asm volatile("ldmatrix.sync.aligned.m8n8.x4.trans.shared.b16 {%0,%1,%2,%3}, [%4];"
                 : "=r"(r0), "=r"(r1), "=r"(r2), "=r"(r3) : "r"(a));
}

// =================================================================
// Kernel 1: Phase A (HMMA) -> WF fp16.  Blocks < 240 also prep KVT.
//   Per warp-point: wf[16k][64f] = wT[16k][32h] @ feat[32h][64f]
// =================================================================
__global__ void __launch_bounds__(THREADS_A)
phaseA_kernel(const float* __restrict__ points,
              const float* __restrict__ features,
              const float* __restrict__ output_points,
              const float* __restrict__ k_points,
              const float* __restrict__ k_values,
              const int*   __restrict__ neighbor_indices)
{
    extern __shared__ __half smA[];
    __shared__ float kps[KK * 3 + 3];

    const int tid  = threadIdx.x;
    const int warp = tid >> 5;
    const int lane = tid & 31;
    const int g    = lane >> 2;
    const int t    = lane & 3;

    // merged KVT prep (240 * 256 = 61440 = KF*CC)
    if (blockIdx.x < 240) {
        const int i = blockIdx.x * THREADS_A + tid;
        const int kf = i >> 6, c = i & 63;
        const float v = k_values[i];
        const __half hi = __float2half_rn(v);
        g_KVThi[c * KF + kf] = hi;
        g_KVTlo[c * KF + kf] = __float2half_rn(v - __half2float(hi));
    }
    if (tid < KK * 3) kps[tid] = k_points[tid];
    __syncthreads();

    __half* featsm = smA + warp * WARP_HALFS;   // [32][FEATW]
    __half* wsmT   = featsm + HH * FEATW;       // [16][WROW] : wT[k][h]
    const uint32_t featb = smem_u32(featsm);
    const uint32_t wb    = smem_u32(wsmT);

    const int gp = blockIdx.x * WARPS_A + warp;
    const int b  = gp >> 14;

    // zero pad row k=15 (h = lane)
    wsmT[15 * WROW + lane] = __ushort_as_half(0);

    // ---- w compute: lane = h, write transposed wT[k][h] fp16 ----
    const int nidx = neighbor_indices[gp * HH + lane];
    const float ox = output_points[gp * 3 + 0];
    const float oy = output_points[gp * 3 + 1];
    const float oz = output_points[gp * 3 + 2];
    const float* pp = points + ((size_t)b * NN + nidx) * 3;
    const float rx = pp[0] - ox;
    const float ry = pp[1] - oy;
    const float rz = pp[2] - oz;

    #pragma unroll
    for (int k = 0; k < KK; k++) {
        const float dx = rx - kps[k * 3 + 0];
        const float dy = ry - kps[k * 3 + 1];
        const float dz = rz - kps[k * 3 + 2];
        const float d  = sqrtf(fmaf(dx, dx, fmaf(dy, dy, dz * dz)));
        wsmT[k * WROW + lane] = __float2half_rn(fmaxf(1.0f - d, 0.0f));
    }

    // ---- gather feat rows as fp16 ----
    const float* fbase = features + (size_t)b * NN * FF;
    #pragma unroll 4
    for (int h = 0; h < HH; h++) {
        const int ni = __shfl_sync(0xffffffffu, nidx, h);
        const float2 fv = *(const float2*)(fbase + (size_t)ni * FF + 2 * lane);
        *(__half2*)(featsm + h * FEATW + 2 * lane) = __floats2half2_rn(fv.x, fv.y);
    }
    __syncwarp();

    // ---- MMA: D[k16][f64] ----
    float acc[8][4];
    #pragma unroll
    for (int nt = 0; nt < 8; nt++)
        #pragma unroll
        for (int q = 0; q < 4; q++) acc[nt][q] = 0.0f;

    // ldmatrix lane-address components
    const int lm_h = ((lane >> 3) & 1) * 8 + (lane & 7);   // kk row within 16
    const int lm_f = ((lane >> 4) & 1) * 8;                // f sub-block

    #pragma unroll
    for (int kstep = 0; kstep < 2; kstep++) {
        const int h0 = kstep * 16;
        uint32_t a[4];
        const uint32_t ab = wb + g * (WROW * 2) + kstep * 32 + t * 4;
        a[0] = lds32(ab);
        a[1] = lds32(ab + 8 * (WROW * 2));
        a[2] = lds32(ab + 16);
        a[3] = lds32(ab + 8 * (WROW * 2) + 16);

        const uint32_t fadr = featb + (h0 + lm_h) * (FEATW * 2) + lm_f * 2;
        #pragma unroll
        for (int fb = 0; fb < 4; fb++) {
            uint32_t r0, r1, r2, r3;
            ldmatrix_x4_t(r0, r1, r2, r3, fadr + fb * 32);
            uint32_t b0[2] = {r0, r1};
            uint32_t b1[2] = {r2, r3};
            mma16816h(acc[fb * 2 + 0], a, b0);
            mma16816h(acc[fb * 2 + 1], a, b1);
        }
    }

    // ---- epilogue: D[g][f], D[g+8][f] -> WF fp16 (skip k=15 pad) ----
    __half2* wdst = (__half2*)(g_WF + (size_t)gp * KF);
    #pragma unroll
    for (int nt = 0; nt < 8; nt++) {
        wdst[g * 32 + nt * 4 + t] = __floats2half2_rn(acc[nt][0], acc[nt][1]);
        if (g < 7)
            wdst[(g + 8) * 32 + nt * 4 + t] = __floats2half2_rn(acc[nt][2], acc[nt][3]);
    }
}

// =================================================================
// Kernel 2: out = WF @ KVT^T, fp16 HMMA, 2-term kv hi/lo, double-buffered
// (unchanged from R6)
// =================================================================
__global__ void __launch_bounds__(THREADS_G, 2)
gemm_kernel(float* __restrict__ out)
{
    extern __shared__ char smem[];
    const uint32_t smb = smem_u32(smem);

    const int tid  = threadIdx.x;
    const int wid  = tid >> 5;
    const int lane = tid & 31;
    const int g    = lane >> 2;
    const int t    = lane & 3;
    const int m0   = blockIdx.x * PTS_CTA;
    const int pbase = wid * 32;

    float acc[4][4][4];
    #pragma unroll
    for (int i = 0; i < 4; i++)
        #pragma unroll
        for (int j = 0; j < 4; j++)
            #pragma unroll
            for (int q = 0; q < 4; q++) acc[i][j][q] = 0.0f;

    auto stage_load = [&](int ch, int buf) {
        const size_t koff = (size_t)ch * KCH;
        const uint32_t sb = smb + buf * ST_SIZE;
        #pragma unroll
        for (int u = tid; u < PTS_CTA * 8; u += THREADS_G) {
            const int r = u >> 3, s = u & 7;
            cpasync16(sb + ST_WF + r * ROWB + s * 16,
                      g_WF + (size_t)(m0 + r) * KF + koff + s * 8);
        }
        #pragma unroll
        for (int u = tid; u < CC * 8; u += THREADS_G) {
            const int r = u >> 3, s = u & 7;
            const size_t src = (size_t)r * KF + koff + s * 8;
            cpasync16(sb + ST_KVHI + r * ROWB + s * 16, g_KVThi + src);
            cpasync16(sb + ST_KVLO + r * ROWB + s * 16, g_KVTlo + src);
        }
        cpasync_commit();
    };

    stage_load(0, 0);

    for (int ch = 0; ch < NCH; ch++) {
        if (ch + 1 < NCH) {
            stage_load(ch + 1, (ch + 1) & 1);
            asm volatile("cp.async.wait_group 1;" ::: "memory");
        } else {
            asm volatile("cp.async.wait_group 0;" ::: "memory");
        }
        __syncthreads();

        const uint32_t sb = smb + (ch & 1) * ST_SIZE;

        #pragma unroll
        for (int ks = 0; ks < KCH / 16; ks++) {
            const int kbB = ks * 32;

            uint32_t bh[4][2];
            #pragma unroll
            for (int pt = 0; pt < 4; pt++) {
                const uint32_t rowoff = (pbase + pt * 8 + g) * ROWB + kbB + t * 4;
                bh[pt][0] = lds32(sb + ST_WF + rowoff);
                bh[pt][1] = lds32(sb + ST_WF + rowoff + 16);
            }

            #pragma unroll
            for (int cm = 0; cm < 4; cm++) {
                const uint32_t rowoff = (cm * 16 + g) * ROWB + kbB + t * 4;
                uint32_t ah[4], al[4];
                ah[0] = lds32(sb + ST_KVHI + rowoff);
                ah[1] = lds32(sb + ST_KVHI + rowoff + 8 * ROWB);
                ah[2] = lds32(sb + ST_KVHI + rowoff + 16);
                ah[3] = lds32(sb + ST_KVHI + rowoff + 8 * ROWB + 16);
                al[0] = lds32(sb + ST_KVLO + rowoff);
                al[1] = lds32(sb + ST_KVLO + rowoff + 8 * ROWB);
                al[2] = lds32(sb + ST_KVLO + rowoff + 16);
                al[3] = lds32(sb + ST_KVLO + rowoff + 8 * ROWB + 16);

                #pragma unroll
                for (int pt = 0; pt < 4; pt++) {
                    mma16816h(acc[cm][pt], ah, bh[pt]);
                    mma16816h(acc[cm][pt], al, bh[pt]);
                }
            }
        }
        __syncthreads();
    }

    #pragma unroll
    for (int cm = 0; cm < 4; cm++) {
        #pragma unroll
        for (int pt = 0; pt < 4; pt++) {
            const int c0 = cm * 16 + g;
            const int c1 = c0 + 8;
            const size_t p0 = (size_t)m0 + pbase + pt * 8 + t * 2;
            out[p0 * CC + c0]       = acc[cm][pt][0];
            out[(p0 + 1) * CC + c0] = acc[cm][pt][1];
            out[p0 * CC + c1]       = acc[cm][pt][2];
            out[(p0 + 1) * CC + c1] = acc[cm][pt][3];
        }
    }
}

// =================================================================
extern "C" void kernel_launch(void* const* d_in, const int* in_sizes, int n_in,
                              void* d_out, int out_size)
{
    const float* points        = (const float*)d_in[0];
    const float* features      = (const float*)d_in[1];
    const float* output_points = (const float*)d_in[2];
    const float* k_points      = (const float*)d_in[3];
    const float* k_values      = (const float*)d_in[4];
    const int*   neighbor_idx  = (const int*)d_in[5];
    float* out = (float*)d_out;

    static bool attr_done = false;
    if (!attr_done) {
        cudaFuncSetAttribute(gemm_kernel, cudaFuncAttributeMaxDynamicSharedMemorySize, SMEM_G);
        cudaFuncSetAttribute(phaseA_kernel, cudaFuncAttributeMaxDynamicSharedMemorySize, SMEM_A);
        attr_done = true;
    }

    phaseA_kernel<<<TOTALP / WARPS_A, THREADS_A, SMEM_A>>>(
        points, features, output_points, k_points, k_values, neighbor_idx);
    gemm_kernel<<<TOTALP / PTS_CTA, THREADS_G, SMEM_G>>>(out);
}

// round 8
// speedup vs baseline: 1.6508x; 1.0458x over previous
#include <cuda_runtime.h>
#include <cuda_fp16.h>
#include <cstdint>

#define BB 4
#define NN 16384
#define MM 16384
#define HH 32
#define KK 15
#define FF 64
#define CC 64
#define KF 960
#define TOTALP (BB * MM)      // 65536

// ---------------- Phase-A (HMMA) config ----------------
#define THREADS_A 256         // 8 warps, 1 point per warp
#define WARPS_A 8
#define FEATW 72              // halfs per feat row (144B)
#define WROW  40              // halfs per wT row (80B)
#define WARP_HALFS (HH * FEATW + 16 * WROW)   // 2944
#define SMEM_A (WARPS_A * WARP_HALFS * 2)     // 47104 B

// ---------------- GEMM config (validated R6/R7) ----------------
#define PTS_CTA 256
#define THREADS_G 256
#define KCH 64
#define NCH (KF / KCH)        // 15
#define ROWB 144

#define ST_WF   0
#define ST_KVHI (PTS_CTA * ROWB)
#define ST_KVLO (ST_KVHI + CC * ROWB)
#define ST_SIZE (ST_KVLO + CC * ROWB)
#define SMEM_G  (2 * ST_SIZE)

// ------------- device scratch -------------
__device__ __half g_WF[(size_t)TOTALP * KF];       // 120 MB fp16
__device__ __half g_feat16[(size_t)BB * NN * FF];  // 8.4 MB fp16 features
__device__ __half g_KVThi[CC * KF];
__device__ __half g_KVTlo[CC * KF];

// ------------- helpers -------------
__device__ __forceinline__ uint32_t smem_u32(const void* p) {
    uint32_t a;
    asm("{ .reg .u64 t; cvta.to.shared.u64 t, %1; cvt.u32.u64 %0, t; }" : "=r"(a) : "l"(p));
    return a;
}
__device__ __forceinline__ void cpasync16(uint32_t dst, const void* src) {
    asm volatile("cp.async.cg.shared.global [%0], [%1], 16;" :: "r"(dst), "l"(src));
}
__device__ __forceinline__ void cpasync_commit() { asm volatile("cp.async.commit_group;"); }
__device__ __forceinline__ uint32_t lds32(uint32_t a) {
    uint32_t v; asm volatile("ld.shared.b32 %0, [%1];" : "=r"(v) : "r"(a)); return v;
}
__device__ __forceinline__ void mma16816h(float* c, const uint32_t* a, const uint32_t* b) {
    asm volatile(
        "mma.sync.aligned.m16n8k16.row.col.f32.f16.f16.f32 "
        "{%0,%1,%2,%3}, {%4,%5,%6,%7}, {%8,%9}, {%0,%1,%2,%3};"
        : "+f"(c[0]), "+f"(c[1]), "+f"(c[2]), "+f"(c[3])
        : "r"(a[0]), "r"(a[1]), "r"(a[2]), "r"(a[3]), "r"(b[0]), "r"(b[1]));
}
__device__ __forceinline__ void ldmatrix_x4_t(uint32_t& r0, uint32_t& r1,
                                              uint32_t& r2, uint32_t& r3, uint32_t a) {
    asm volatile("ldmatrix.sync.aligned.m8n8.x4.trans.shared.b16 {%0,%1,%2,%3}, [%4];"
                 : "=r"(r0), "=r"(r1), "=r"(r2), "=r"(r3) : "r"(a));
}

// =================================================================
// Kernel 0: features fp32 -> fp16 (streaming)
// =================================================================
__global__ void prep_feat16_kernel(const float* __restrict__ features) {
    const int i = blockIdx.x * blockDim.x + threadIdx.x;   // over elems/4
    const float4 v = ((const float4*)features)[i];
    __half2 a = __floats2half2_rn(v.x, v.y);
    __half2 b = __floats2half2_rn(v.z, v.w);
    ((__half2*)g_feat16)[2 * i]     = a;
    ((__half2*)g_feat16)[2 * i + 1] = b;
}

// =================================================================
// Kernel 1: Phase A (HMMA) -> WF fp16.  Blocks < 240 also prep KVT.
// =================================================================
__global__ void __launch_bounds__(THREADS_A)
phaseA_kernel(const float* __restrict__ points,
              const float* __restrict__ output_points,
              const float* __restrict__ k_points,
              const float* __restrict__ k_values,
              const int*   __restrict__ neighbor_indices)
{
    extern __shared__ __half smA[];
    __shared__ float kps[KK * 3 + 3];

    const int tid  = threadIdx.x;
    const int warp = tid >> 5;
    const int lane = tid & 31;
    const int g    = lane >> 2;
    const int t    = lane & 3;

    if (blockIdx.x < 240) {
        const int i = blockIdx.x * THREADS_A + tid;
        const int kf = i >> 6, c = i & 63;
        const float v = k_values[i];
        const __half hi = __float2half_rn(v);
        g_KVThi[c * KF + kf] = hi;
        g_KVTlo[c * KF + kf] = __float2half_rn(v - __half2float(hi));
    }
    if (tid < KK * 3) kps[tid] = k_points[tid];
    __syncthreads();

    __half* featsm = smA + warp * WARP_HALFS;   // [32][FEATW]
    __half* wsmT   = featsm + HH * FEATW;       // [16][WROW]
    const uint32_t featb = smem_u32(featsm);
    const uint32_t wb    = smem_u32(wsmT);

    const int gp = blockIdx.x * WARPS_A + warp;
    const int b  = gp >> 14;

    wsmT[15 * WROW + lane] = __ushort_as_half(0);

    // ---- w compute: lane = h ----
    const int nidx = neighbor_indices[gp * HH + lane];
    const float ox = output_points[gp * 3 + 0];
    const float oy = output_points[gp * 3 + 1];
    const float oz = output_points[gp * 3 + 2];
    const float* pp = points + ((size_t)b * NN + nidx) * 3;
    const float rx = pp[0] - ox;
    const float ry = pp[1] - oy;
    const float rz = pp[2] - oz;

    #pragma unroll
    for (int k = 0; k < KK; k++) {
        const float dx = rx - kps[k * 3 + 0];
        const float dy = ry - kps[k * 3 + 1];
        const float dz = rz - kps[k * 3 + 2];
        const float d  = sqrtf(fmaf(dx, dx, fmaf(dy, dy, dz * dz)));
        wsmT[k * WROW + lane] = __float2half_rn(fmaxf(1.0f - d, 0.0f));
    }

    // ---- gather fp16 feat rows: 4 rows / iter, LDG.128 per lane ----
    const __half* f16base = g_feat16 + (size_t)b * NN * FF;
    const int s = lane & 7;            // 16B slot in row
    #pragma unroll
    for (int it = 0; it < 8; it++) {
        const int row = it * 4 + (lane >> 3);
        const int ni  = __shfl_sync(0xffffffffu, nidx, row);
        const uint4 v = *(const uint4*)(f16base + (size_t)ni * FF + s * 8);
        *(uint4*)(featsm + row * FEATW + s * 8) = v;
    }
    __syncwarp();

    // ---- MMA: D[k16][f64] ----
    float acc[8][4];
    #pragma unroll
    for (int nt = 0; nt < 8; nt++)
        #pragma unroll
        for (int q = 0; q < 4; q++) acc[nt][q] = 0.0f;

    const int lm_h = ((lane >> 3) & 1) * 8 + (lane & 7);
    const int lm_f = ((lane >> 4) & 1) * 8;

    #pragma unroll
    for (int kstep = 0; kstep < 2; kstep++) {
        const int h0 = kstep * 16;
        uint32_t a[4];
        const uint32_t ab = wb + g * (WROW * 2) + kstep * 32 + t * 4;
        a[0] = lds32(ab);
        a[1] = lds32(ab + 8 * (WROW * 2));
        a[2] = lds32(ab + 16);
        a[3] = lds32(ab + 8 * (WROW * 2) + 16);

        const uint32_t fadr = featb + (h0 + lm_h) * (FEATW * 2) + lm_f * 2;
        #pragma unroll
        for (int fb = 0; fb < 4; fb++) {
            uint32_t r0, r1, r2, r3;
            ldmatrix_x4_t(r0, r1, r2, r3, fadr + fb * 32);
            uint32_t b0[2] = {r0, r1};
            uint32_t b1[2] = {r2, r3};
            mma16816h(acc[fb * 2 + 0], a, b0);
            mma16816h(acc[fb * 2 + 1], a, b1);
        }
    }

    // ---- epilogue ----
    __half2* wdst = (__half2*)(g_WF + (size_t)gp * KF);
    #pragma unroll
    for (int nt = 0; nt < 8; nt++) {
        wdst[g * 32 + nt * 4 + t] = __floats2half2_rn(acc[nt][0], acc[nt][1]);
        if (g < 7)
            wdst[(g + 8) * 32 + nt * 4 + t] = __floats2half2_rn(acc[nt][2], acc[nt][3]);
    }
}

// =================================================================
// Kernel 2: out = WF @ KVT^T (unchanged from R6/R7)
// =================================================================
__global__ void __launch_bounds__(THREADS_G, 2)
gemm_kernel(float* __restrict__ out)
{
    extern __shared__ char smem[];
    const uint32_t smb = smem_u32(smem);

    const int tid  = threadIdx.x;
    const int wid  = tid >> 5;
    const int lane = tid & 31;
    const int g    = lane >> 2;
    const int t    = lane & 3;
    const int m0   = blockIdx.x * PTS_CTA;
    const int pbase = wid * 32;

    float acc[4][4][4];
    #pragma unroll
    for (int i = 0; i < 4; i++)
        #pragma unroll
        for (int j = 0; j < 4; j++)
            #pragma unroll
            for (int q = 0; q < 4; q++) acc[i][j][q] = 0.0f;

    auto stage_load = [&](int ch, int buf) {
        const size_t koff = (size_t)ch * KCH;
        const uint32_t sb = smb + buf * ST_SIZE;
        #pragma unroll
        for (int u = tid; u < PTS_CTA * 8; u += THREADS_G) {
            const int r = u >> 3, s = u & 7;
            cpasync16(sb + ST_WF + r * ROWB + s * 16,
                      g_WF + (size_t)(m0 + r) * KF + koff + s * 8);
        }
        #pragma unroll
        for (int u = tid; u < CC * 8; u += THREADS_G) {
            const int r = u >> 3, s = u & 7;
            const size_t src = (size_t)r * KF + koff + s * 8;
            cpasync16(sb + ST_KVHI + r * ROWB + s * 16, g_KVThi + src);
            cpasync16(sb + ST_KVLO + r * ROWB + s * 16, g_KVTlo + src);
        }
        cpasync_commit();
    };

    stage_load(0, 0);

    for (int ch = 0; ch < NCH; ch++) {
        if (ch + 1 < NCH) {
            stage_load(ch + 1, (ch + 1) & 1);
            asm volatile("cp.async.wait_group 1;" ::: "memory");
        } else {
            asm volatile("cp.async.wait_group 0;" ::: "memory");
        }
        __syncthreads();

        const uint32_t sb = smb + (ch & 1) * ST_SIZE;

        #pragma unroll
        for (int ks = 0; ks < KCH / 16; ks++) {
            const int kbB = ks * 32;

            uint32_t bh[4][2];
            #pragma unroll
            for (int pt = 0; pt < 4; pt++) {
                const uint32_t rowoff = (pbase + pt * 8 + g) * ROWB + kbB + t * 4;
                bh[pt][0] = lds32(sb + ST_WF + rowoff);
                bh[pt][1] = lds32(sb + ST_WF + rowoff + 16);
            }

            #pragma unroll
            for (int cm = 0; cm < 4; cm++) {
                const uint32_t rowoff = (cm * 16 + g) * ROWB + kbB + t * 4;
                uint32_t ah[4], al[4];
                ah[0] = lds32(sb + ST_KVHI + rowoff);
                ah[1] = lds32(sb + ST_KVHI + rowoff + 8 * ROWB);
                ah[2] = lds32(sb + ST_KVHI + rowoff + 16);
                ah[3] = lds32(sb + ST_KVHI + rowoff + 8 * ROWB + 16);
                al[0] = lds32(sb + ST_KVLO + rowoff);
                al[1] = lds32(sb + ST_KVLO + rowoff + 8 * ROWB);
                al[2] = lds32(sb + ST_KVLO + rowoff + 16);
                al[3] = lds32(sb + ST_KVLO + rowoff + 8 * ROWB + 16);

                #pragma unroll
                for (int pt = 0; pt < 4; pt++) {
                    mma16816h(acc[cm][pt], ah, bh[pt]);
                    mma16816h(acc[cm][pt], al, bh[pt]);
                }
            }
        }
        __syncthreads();
    }

    #pragma unroll
    for (int cm = 0; cm < 4; cm++) {
        #pragma unroll
        for (int pt = 0; pt < 4; pt++) {
            const int c0 = cm * 16 + g;
            const int c1 = c0 + 8;
            const size_t p0 = (size_t)m0 + pbase + pt * 8 + t * 2;
            out[p0 * CC + c0]       = acc[cm][pt][0];
            out[(p0 + 1) * CC + c0] = acc[cm][pt][1];
            out[p0 * CC + c1]       = acc[cm][pt][2];
            out[(p0 + 1) * CC + c1] = acc[cm][pt][3];
        }
    }
}

// =================================================================
extern "C" void kernel_launch(void* const* d_in, const int* in_sizes, int n_in,
                              void* d_out, int out_size)
{
    const float* points        = (const float*)d_in[0];
    const float* features      = (const float*)d_in[1];
    const float* output_points = (const float*)d_in[2];
    const float* k_points      = (const float*)d_in[3];
    const float* k_values      = (const float*)d_in[4];
    const int*   neighbor_idx  = (const int*)d_in[5];
    float* out = (float*)d_out;

    static bool attr_done = false;
    if (!attr_done) {
        cudaFuncSetAttribute(gemm_kernel, cudaFuncAttributeMaxDynamicSharedMemorySize, SMEM_G);
        cudaFuncSetAttribute(phaseA_kernel, cudaFuncAttributeMaxDynamicSharedMemorySize, SMEM_A);
        attr_done = true;
    }

    const int feat_elems4 = BB * NN * FF / 4;   // float4 count
    prep_feat16_kernel<<<feat_elems4 / 256, 256>>>(features);
    phaseA_kernel<<<TOTALP / WARPS_A, THREADS_A, SMEM_A>>>(
        points, output_points, k_points, k_values, neighbor_idx);
    gemm_kernel<<<TOTALP / PTS_CTA, THREADS_G, SMEM_G>>>(out);
}

// round 9
// speedup vs baseline: 2.0966x; 1.2700x over previous
#include <cuda_runtime.h>
#include <cuda_fp16.h>
#include <cstdint>

#define BB 4
#define NN 16384
#define MM 16384
#define HH 32
#define KK 15
#define FF 64
#define CC 64
#define KF 960
#define TOTALP (BB * MM)      // 65536

// ---------------- Phase-A (HMMA) config ----------------
#define THREADS_A 256         // 8 warps, 1 point per warp
#define WARPS_A 8
#define FEATW 72              // halfs per feat row (144B)
#define WROW  40              // halfs per wT row (80B)
#define WARP_HALFS (HH * FEATW + 16 * WROW)   // 2944
#define SMEM_A (WARPS_A * WARP_HALFS * 2)     // 47104 B

// ---------------- GEMM config ----------------
#define PTS_CTA 256
#define THREADS_G 256
#define KCH 64
#define NCH (KF / KCH)        // 15
#define ROWB 144

#define ST_WF   0
#define ST_KV   (PTS_CTA * ROWB)            // 36864
#define ST_SIZE (ST_KV + CC * ROWB)         // 46080
#define SMEM_G  (2 * ST_SIZE)               // 92160

// ------------- device scratch -------------
__device__ __half g_WF[(size_t)TOTALP * KF];       // 120 MB fp16
__device__ __half g_feat16[(size_t)BB * NN * FF];  // 8.4 MB fp16 features
__device__ __half g_KVT[CC * KF];                  // [c][kf] fp16

// ------------- helpers -------------
__device__ __forceinline__ uint32_t smem_u32(const void* p) {
    uint32_t a;
    asm("{ .reg .u64 t; cvta.to.shared.u64 t, %1; cvt.u32.u64 %0, t; }" : "=r"(a) : "l"(p));
    return a;
}
__device__ __forceinline__ void cpasync16(uint32_t dst, const void* src) {
    asm volatile("cp.async.cg.shared.global [%0], [%1], 16;" :: "r"(dst), "l"(src));
}
__device__ __forceinline__ void cpasync_commit() { asm volatile("cp.async.commit_group;"); }
__device__ __forceinline__ void cpasync_wait_all() {
    asm volatile("cp.async.wait_group 0;" ::: "memory");
}
__device__ __forceinline__ uint32_t lds32(uint32_t a) {
    uint32_t v; asm volatile("ld.shared.b32 %0, [%1];" : "=r"(v) : "r"(a)); return v;
}
__device__ __forceinline__ void mma16816h(float* c, const uint32_t* a, const uint32_t* b) {
    asm volatile(
        "mma.sync.aligned.m16n8k16.row.col.f32.f16.f16.f32 "
        "{%0,%1,%2,%3}, {%4,%5,%6,%7}, {%8,%9}, {%0,%1,%2,%3};"
        : "+f"(c[0]), "+f"(c[1]), "+f"(c[2]), "+f"(c[3])
        : "r"(a[0]), "r"(a[1]), "r"(a[2]), "r"(a[3]), "r"(b[0]), "r"(b[1]));
}
__device__ __forceinline__ void ldmatrix_x4_t(uint32_t& r0, uint32_t& r1,
                                              uint32_t& r2, uint32_t& r3, uint32_t a) {
    asm volatile("ldmatrix.sync.aligned.m8n8.x4.trans.shared.b16 {%0,%1,%2,%3}, [%4];"
                 : "=r"(r0), "=r"(r1), "=r"(r2), "=r"(r3) : "r"(a));
}

// =================================================================
// Kernel 0: features fp32 -> fp16 (streaming)
// =================================================================
__global__ void prep_feat16_kernel(const float* __restrict__ features) {
    const int i = blockIdx.x * blockDim.x + threadIdx.x;
    const float4 v = ((const float4*)features)[i];
    ((__half2*)g_feat16)[2 * i]     = __floats2half2_rn(v.x, v.y);
    ((__half2*)g_feat16)[2 * i + 1] = __floats2half2_rn(v.z, v.w);
}

// =================================================================
// Kernel 1: Phase A (HMMA) -> WF fp16.  Blocks < 240 also prep KVT.
//   cp.async gather overlapped with w/sqrt compute.
// =================================================================
__global__ void __launch_bounds__(THREADS_A, 3)
phaseA_kernel(const float* __restrict__ points,
              const float* __restrict__ output_points,
              const float* __restrict__ k_points,
              const float* __restrict__ k_values,
              const int*   __restrict__ neighbor_indices)
{
    extern __shared__ __half smA[];
    __shared__ float kps[KK * 3 + 3];

    const int tid  = threadIdx.x;
    const int warp = tid >> 5;
    const int lane = tid & 31;
    const int g    = lane >> 2;
    const int t    = lane & 3;

    // merged KVT prep (240 * 256 = 61440 = KF*CC), single fp16
    if (blockIdx.x < 240) {
        const int i = blockIdx.x * THREADS_A + tid;
        const int kf = i >> 6, c = i & 63;
        g_KVT[c * KF + kf] = __float2half_rn(k_values[i]);
    }
    if (tid < KK * 3) kps[tid] = k_points[tid];
    __syncthreads();

    __half* featsm = smA + warp * WARP_HALFS;   // [32][FEATW]
    __half* wsmT   = featsm + HH * FEATW;       // [16][WROW]
    const uint32_t featb = smem_u32(featsm);
    const uint32_t wb    = smem_u32(wsmT);

    const int gp = blockIdx.x * WARPS_A + warp;
    const int b  = gp >> 14;

    // ---- load neighbor idx, immediately issue gather cp.asyncs ----
    const int nidx = neighbor_indices[gp * HH + lane];
    const __half* f16base = g_feat16 + (size_t)b * NN * FF;
    const int s = lane & 7;
    #pragma unroll
    for (int it = 0; it < 8; it++) {
        const int row = it * 4 + (lane >> 3);
        const int ni  = __shfl_sync(0xffffffffu, nidx, row);
        cpasync16(featb + row * (FEATW * 2) + s * 16,
                  f16base + (size_t)ni * FF + s * 8);
    }
    cpasync_commit();

    // ---- w compute (overlaps gather latency): lane = h ----
    wsmT[15 * WROW + lane] = __ushort_as_half(0);
    const float ox = output_points[gp * 3 + 0];
    const float oy = output_points[gp * 3 + 1];
    const float oz = output_points[gp * 3 + 2];
    const float* pp = points + ((size_t)b * NN + nidx) * 3;
    const float rx = pp[0] - ox;
    const float ry = pp[1] - oy;
    const float rz = pp[2] - oz;

    #pragma unroll
    for (int k = 0; k < KK; k++) {
        const float dx = rx - kps[k * 3 + 0];
        const float dy = ry - kps[k * 3 + 1];
        const float dz = rz - kps[k * 3 + 2];
        const float d  = sqrtf(fmaf(dx, dx, fmaf(dy, dy, dz * dz)));
        wsmT[k * WROW + lane] = __float2half_rn(fmaxf(1.0f - d, 0.0f));
    }

    cpasync_wait_all();
    __syncwarp();

    // ---- MMA: D[k16][f64] ----
    float acc[8][4];
    #pragma unroll
    for (int nt = 0; nt < 8; nt++)
        #pragma unroll
        for (int q = 0; q < 4; q++) acc[nt][q] = 0.0f;

    const int lm_h = ((lane >> 3) & 1) * 8 + (lane & 7);
    const int lm_f = ((lane >> 4) & 1) * 8;

    #pragma unroll
    for (int kstep = 0; kstep < 2; kstep++) {
        const int h0 = kstep * 16;
        uint32_t a[4];
        const uint32_t ab = wb + g * (WROW * 2) + kstep * 32 + t * 4;
        a[0] = lds32(ab);
        a[1] = lds32(ab + 8 * (WROW * 2));
        a[2] = lds32(ab + 16);
        a[3] = lds32(ab + 8 * (WROW * 2) + 16);

        const uint32_t fadr = featb + (h0 + lm_h) * (FEATW * 2) + lm_f * 2;
        #pragma unroll
        for (int fb = 0; fb < 4; fb++) {
            uint32_t r0, r1, r2, r3;
            ldmatrix_x4_t(r0, r1, r2, r3, fadr + fb * 32);
            uint32_t b0[2] = {r0, r1};
            uint32_t b1[2] = {r2, r3};
            mma16816h(acc[fb * 2 + 0], a, b0);
            mma16816h(acc[fb * 2 + 1], a, b1);
        }
    }

    // ---- epilogue ----
    __half2* wdst = (__half2*)(g_WF + (size_t)gp * KF);
    #pragma unroll
    for (int nt = 0; nt < 8; nt++) {
        wdst[g * 32 + nt * 4 + t] = __floats2half2_rn(acc[nt][0], acc[nt][1]);
        if (g < 7)
            wdst[(g + 8) * 32 + nt * 4 + t] = __floats2half2_rn(acc[nt][2], acc[nt][3]);
    }
}

// =================================================================
// Kernel 2: out = WF @ KVT^T, single-term fp16 HMMA, double-buffered
// =================================================================
__global__ void __launch_bounds__(THREADS_G, 2)
gemm_kernel(float* __restrict__ out)
{
    extern __shared__ char smem[];
    const uint32_t smb = smem_u32(smem);

    const int tid  = threadIdx.x;
    const int wid  = tid >> 5;
    const int lane = tid & 31;
    const int g    = lane >> 2;
    const int t    = lane & 3;
    const int m0   = blockIdx.x * PTS_CTA;
    const int pbase = wid * 32;

    float acc[4][4][4];
    #pragma unroll
    for (int i = 0; i < 4; i++)
        #pragma unroll
        for (int j = 0; j < 4; j++)
            #pragma unroll
            for (int q = 0; q < 4; q++) acc[i][j][q] = 0.0f;

    auto stage_load = [&](int ch, int buf) {
        const size_t koff = (size_t)ch * KCH;
        const uint32_t sb = smb + buf * ST_SIZE;
        #pragma unroll
        for (int u = tid; u < PTS_CTA * 8; u += THREADS_G) {
            const int r = u >> 3, s = u & 7;
            cpasync16(sb + ST_WF + r * ROWB + s * 16,
                      g_WF + (size_t)(m0 + r) * KF + koff + s * 8);
        }
        #pragma unroll
        for (int u = tid; u < CC * 8; u += THREADS_G) {
            const int r = u >> 3, s = u & 7;
            cpasync16(sb + ST_KV + r * ROWB + s * 16,
                      g_KVT + (size_t)r * KF + koff + s * 8);
        }
        cpasync_commit();
    };

    stage_load(0, 0);

    for (int ch = 0; ch < NCH; ch++) {
        if (ch + 1 < NCH) {
            stage_load(ch + 1, (ch + 1) & 1);
            asm volatile("cp.async.wait_group 1;" ::: "memory");
        } else {
            asm volatile("cp.async.wait_group 0;" ::: "memory");
        }
        __syncthreads();

        const uint32_t sb = smb + (ch & 1) * ST_SIZE;

        #pragma unroll
        for (int ks = 0; ks < KCH / 16; ks++) {
            const int kbB = ks * 32;

            uint32_t bh[4][2];
            #pragma unroll
            for (int pt = 0; pt < 4; pt++) {
                const uint32_t rowoff = (pbase + pt * 8 + g) * ROWB + kbB + t * 4;
                bh[pt][0] = lds32(sb + ST_WF + rowoff);
                bh[pt][1] = lds32(sb + ST_WF + rowoff + 16);
            }

            #pragma unroll
            for (int cm = 0; cm < 4; cm++) {
                const uint32_t rowoff = (cm * 16 + g) * ROWB + kbB + t * 4;
                uint32_t ah[4];
                ah[0] = lds32(sb + ST_KV + rowoff);
                ah[1] = lds32(sb + ST_KV + rowoff + 8 * ROWB);
                ah[2] = lds32(sb + ST_KV + rowoff + 16);
                ah[3] = lds32(sb + ST_KV + rowoff + 8 * ROWB + 16);

                #pragma unroll
                for (int pt = 0; pt < 4; pt++)
                    mma16816h(acc[cm][pt], ah, bh[pt]);
            }
        }
        __syncthreads();
    }

    #pragma unroll
    for (int cm = 0; cm < 4; cm++) {
        #pragma unroll
        for (int pt = 0; pt < 4; pt++) {
            const int c0 = cm * 16 + g;
            const int c1 = c0 + 8;
            const size_t p0 = (size_t)m0 + pbase + pt * 8 + t * 2;
            out[p0 * CC + c0]       = acc[cm][pt][0];
            out[(p0 + 1) * CC + c0] = acc[cm][pt][1];
            out[p0 * CC + c1]       = acc[cm][pt][2];
            out[(p0 + 1) * CC + c1] = acc[cm][pt][3];
        }
    }
}

// =================================================================
extern "C" void kernel_launch(void* const* d_in, const int* in_sizes, int n_in,
                              void* d_out, int out_size)
{
    const float* points        = (const float*)d_in[0];
    const float* features      = (const float*)d_in[1];
    const float* output_points = (const float*)d_in[2];
    const float* k_points      = (const float*)d_in[3];
    const float* k_values      = (const float*)d_in[4];
    const int*   neighbor_idx  = (const int*)d_in[5];
    float* out = (float*)d_out;

    static bool attr_done = false;
    if (!attr_done) {
        cudaFuncSetAttribute(gemm_kernel, cudaFuncAttributeMaxDynamicSharedMemorySize, SMEM_G);
        cudaFuncSetAttribute(phaseA_kernel, cudaFuncAttributeMaxDynamicSharedMemorySize, SMEM_A);
        attr_done = true;
    }

    const int feat_elems4 = BB * NN * FF / 4;
    prep_feat16_kernel<<<feat_elems4 / 256, 256>>>(features);
    phaseA_kernel<<<TOTALP / WARPS_A, THREADS_A, SMEM_A>>>(
        points, output_points, k_points, k_values, neighbor_idx);
    gemm_kernel<<<TOTALP / PTS_CTA, THREADS_G, SMEM_G>>>(out);
}